// round 13
// baseline (speedup 1.0000x reference)
#include <cuda_runtime.h>
#include <mma.h>
#include <math.h>
#include <stdint.h>

#define NE 7
#define TOPK 2
#define CAPACITY 3072
#define DM 1024
#define DFF 4096
#define NT 8192
#define TK (NT*TOPK)
#define NSEG 64                // TK / 256

#define MT1 (CAPACITY/256)    // 12 m-tiles (256 rows each)
#define NT1 (DFF/256)         // 16 256-wide n-tiles (chunk layout)
#define NT2 (DM/256)          // 4
#define NCH1 (DM/32)          // 32 k-chunks (GEMM1)
#define NCH2 (DFF/32)         // 128 k-chunks (GEMM2)
#define CHUNK_BYTES 32768     // 256 rows x 128B
#define HALF_BYTES  16384     // 128 rows x 128B

#if defined(__CUDA_ARCH__) && defined(__CUDA_ARCH_FEAT_SM103_ALL)
#define HAS_TC 1
#else
#define HAS_TC 0
#endif

// ---------------- scratch (device globals; no allocations allowed) ----------
__device__ int   g_te[TK];
__device__ float g_tw[TK];
__device__ int   g_src[NE*CAPACITY];
__device__ int   g_cnt[NE];
__device__ int   g_run[NE];
__device__ int   g_blkcnt[NSEG*NE];
__device__ int   g_segoff[NSEG*NE];
__device__ int   g_cidx[TK];
__device__ float g_cw[TK];
__device__ float g_abuf[(size_t)NE*MT1*NCH1*8192];   // x gathered, chunked+swizzled
__device__ float g_w1t[(size_t)NE*(size_t)DFF*DM];   // W1^T chunked [e][nt256][k][32KB]
__device__ float g_w2t[(size_t)NE*(size_t)DM*DFF];   // W2^T chunked [e][nt256][k][32KB]
__device__ float g_h[(size_t)NE*CAPACITY*DFF];       // h chunked (TC) / row-major (fallback)
__device__ float g_y[(size_t)NE*CAPACITY*DM];        // row-major

// ---------------- common helpers ---------------------------------------------
__device__ __forceinline__ float to_tf32(float f) {
    float r; asm("cvt.rna.tf32.f32 %0, %1;" : "=f"(r) : "f"(f)); return r;
}
__device__ __forceinline__ float gelu_tanh(float v) {
    float c = 0.7978845608028654f * (v + 0.044715f * v * v * v);
    return 0.5f * v * (1.f + tanhf(c));
}
__device__ __forceinline__ uint32_t smem_u32(const void* p) {
    uint32_t a;
    asm("{ .reg .u64 t; cvta.to.shared.u64 t, %1; cvt.u32.u64 %0, t; }" : "=r"(a) : "l"(p));
    return a;
}
__device__ __forceinline__ uint32_t swz(uint32_t b) { return b ^ ((b >> 3) & 0x70); }

#if HAS_TC
// ---------------- tcgen05 / TMA-bulk PTX helpers ------------------------------
__device__ __forceinline__ void bulk_g2s(uint32_t dst, const void* src, uint32_t bytes,
                                         uint32_t mbar) {
    asm volatile(
        "cp.async.bulk.shared::cluster.global.mbarrier::complete_tx::bytes [%0], [%1], %2, [%3];"
        :: "r"(dst), "l"(src), "r"(bytes), "r"(mbar) : "memory");
}
__device__ __forceinline__ void mbar_init(uint32_t a, uint32_t cnt) {
    asm volatile("mbarrier.init.shared.b64 [%0], %1;" :: "r"(a), "r"(cnt) : "memory");
}
__device__ __forceinline__ void mbar_expect_tx(uint32_t a, uint32_t bytes) {
    asm volatile("mbarrier.arrive.expect_tx.shared.b64 _, [%0], %1;" :: "r"(a), "r"(bytes) : "memory");
}
__device__ __forceinline__ void mbar_wait(uint32_t a, uint32_t parity) {
    asm volatile(
        "{\n\t.reg .pred P;\n\t"
        "WAITLOOP_%=:\n\t"
        "mbarrier.try_wait.parity.acquire.cta.shared::cta.b64 P, [%0], %1, 0x989680;\n\t"
        "@P bra.uni WDONE_%=;\n\t"
        "bra.uni WAITLOOP_%=;\n\t"
        "WDONE_%=:\n\t}"
        :: "r"(a), "r"(parity) : "memory");
}
__device__ __forceinline__ void mbar_wait_cluster(uint32_t a, uint32_t parity) {
    asm volatile(
        "{\n\t.reg .pred P;\n\t"
        "WAITLOOP_%=:\n\t"
        "mbarrier.try_wait.parity.acquire.cluster.shared::cta.b64 P, [%0], %1, 0x989680;\n\t"
        "@P bra.uni WDONE_%=;\n\t"
        "bra.uni WAITLOOP_%=;\n\t"
        "WDONE_%=:\n\t}"
        :: "r"(a), "r"(parity) : "memory");
}
__device__ __forceinline__ void mbar_arrive_rank0(uint32_t local_addr) {
    asm volatile(
        "{\n\t.reg .b32 r;\n\t"
        "mapa.shared::cluster.u32 r, %0, 0;\n\t"
        "mbarrier.arrive.release.cluster.shared::cluster.b64 _, [r];\n\t}"
        :: "r"(local_addr) : "memory");
}
__device__ __forceinline__ uint32_t cluster_rank() {
    uint32_t r; asm("mov.u32 %0, %%cluster_ctarank;" : "=r"(r)); return r;
}
#define CLUSTER_SYNC() do { \
    asm volatile("barrier.cluster.arrive.aligned;" ::: "memory"); \
    asm volatile("barrier.cluster.wait.aligned;" ::: "memory"); \
} while(0)

#define TC_ALLOC_CG2(smaddr, n)  asm volatile("tcgen05.alloc.cta_group::2.sync.aligned.shared::cta.b32 [%0], %1;" :: "r"(smaddr), "r"((uint32_t)(n)) : "memory")
#define TC_DEALLOC_CG2(tm, n)    asm volatile("tcgen05.dealloc.cta_group::2.sync.aligned.b32 %0, %1;" :: "r"(tm), "r"((uint32_t)(n)))
#define TC_RELINQ_CG2()          asm volatile("tcgen05.relinquish_alloc_permit.cta_group::2.sync.aligned;")
#define TC_COMMIT_MC2(mb, mask)  asm volatile("tcgen05.commit.cta_group::2.mbarrier::arrive::one.shared::cluster.multicast::cluster.b64 [%0], %1;" :: "r"(mb), "h"((uint16_t)(mask)) : "memory")
#define TC_WAIT_LD()             asm volatile("tcgen05.wait::ld.sync.aligned;" ::: "memory")
#define TC_FENCE_BEFORE()        asm volatile("tcgen05.fence::before_thread_sync;" ::: "memory")
#define TC_FENCE_AFTER()         asm volatile("tcgen05.fence::after_thread_sync;" ::: "memory")
#define FENCE_ASYNC_SHARED()     asm volatile("fence.proxy.async.shared::cta;" ::: "memory")

__device__ __forceinline__ void mma_tf32_ss_cg2(uint32_t d, uint64_t ad, uint64_t bd,
                                                uint32_t idesc, uint32_t en) {
    asm volatile(
        "{\n\t.reg .pred p;\n\t"
        "setp.ne.u32 p, %4, 0;\n\t"
        "tcgen05.mma.cta_group::2.kind::tf32 [%0], %1, %2, %3, p;\n\t}"
        :: "r"(d), "l"(ad), "l"(bd), "r"(idesc), "r"(en) : "memory");
}
// K-major SW128 smem descriptor (LBO=1, SBO=64, version=1, layout=SW128)
__device__ __forceinline__ uint64_t mkdesc(uint32_t addr) {
    return (uint64_t)((addr >> 4) & 0x3FFF)
         | (1ull << 16) | (64ull << 32) | (1ull << 46) | (2ull << 61);
}
#define TC_LD_X32(r, tm) \
    asm volatile( \
        "tcgen05.ld.sync.aligned.32x32b.x32.b32 " \
        "{%0, %1, %2, %3, %4, %5, %6, %7, " \
        " %8, %9, %10, %11, %12, %13, %14, %15, " \
        " %16, %17, %18, %19, %20, %21, %22, %23, " \
        " %24, %25, %26, %27, %28, %29, %30, %31}, [%32];" \
        : "=r"((r)[0]),  "=r"((r)[1]),  "=r"((r)[2]),  "=r"((r)[3]), \
          "=r"((r)[4]),  "=r"((r)[5]),  "=r"((r)[6]),  "=r"((r)[7]), \
          "=r"((r)[8]),  "=r"((r)[9]),  "=r"((r)[10]), "=r"((r)[11]), \
          "=r"((r)[12]), "=r"((r)[13]), "=r"((r)[14]), "=r"((r)[15]), \
          "=r"((r)[16]), "=r"((r)[17]), "=r"((r)[18]), "=r"((r)[19]), \
          "=r"((r)[20]), "=r"((r)[21]), "=r"((r)[22]), "=r"((r)[23]), \
          "=r"((r)[24]), "=r"((r)[25]), "=r"((r)[26]), "=r"((r)[27]), \
          "=r"((r)[28]), "=r"((r)[29]), "=r"((r)[30]), "=r"((r)[31]) \
        : "r"(tm))
#endif  // HAS_TC

// ---------------- router ------------------------------------------------------
__global__ void __launch_bounds__(256) router_kernel(const float* __restrict__ x,
                                                     const float* __restrict__ Wg) {
    int wid  = threadIdx.x >> 5;
    int lane = threadIdx.x & 31;
    int t = blockIdx.x * 8 + wid;
    if (t >= NT) return;

    float acc[NE];
#pragma unroll
    for (int e = 0; e < NE; e++) acc[e] = 0.f;

    const float4* xr = reinterpret_cast<const float4*>(x + (size_t)t * DM);
#pragma unroll 4
    for (int i = lane; i < DM / 4; i += 32) {
        float4 v = xr[i];
        int d = i * 4;
#pragma unroll
        for (int e = 0; e < NE; e++) {
            acc[e] += v.x * Wg[(d + 0) * NE + e];
            acc[e] += v.y * Wg[(d + 1) * NE + e];
            acc[e] += v.z * Wg[(d + 2) * NE + e];
            acc[e] += v.w * Wg[(d + 3) * NE + e];
        }
    }
#pragma unroll
    for (int e = 0; e < NE; e++)
#pragma unroll
        for (int off = 16; off > 0; off >>= 1)
            acc[e] += __shfl_xor_sync(0xffffffffu, acc[e], off);

    if (lane == 0) {
        float l0 = -1e30f; int e0 = 0;
#pragma unroll
        for (int e = 0; e < NE; e++) if (acc[e] > l0) { l0 = acc[e]; e0 = e; }
        float l1 = -1e30f; int e1 = 0;
#pragma unroll
        for (int e = 0; e < NE; e++) if (e != e0 && acc[e] > l1) { l1 = acc[e]; e1 = e; }
        float w0 = 1.f / (1.f + __expf(l1 - l0));
        g_te[2 * t]     = e0;  g_te[2 * t + 1] = e1;
        g_tw[2 * t]     = w0;  g_tw[2 * t + 1] = 1.f - w0;
    }
}

// ---------------- parallel ordered capacity scan ------------------------------
__global__ void __launch_bounds__(256) hist_kernel() {
    __shared__ int s_wtot[8][NE];
    int tid = threadIdx.x, wid = tid >> 5, lane = tid & 31;
    int i = blockIdx.x * 256 + tid;
    int e = g_te[i];
#pragma unroll
    for (int ee = 0; ee < NE; ee++) {
        unsigned m = __ballot_sync(0xffffffffu, e == ee);
        if (lane == 0) s_wtot[wid][ee] = __popc(m);
    }
    __syncthreads();
    if (tid < NE) {
        int tot = 0;
#pragma unroll
        for (int w = 0; w < 8; w++) tot += s_wtot[w][tid];
        g_blkcnt[blockIdx.x * NE + tid] = tot;
    }
}

__global__ void __launch_bounds__(32) prefix_kernel() {
    int e = threadIdx.x;
    if (e >= NE) return;
    int run = 0;
    for (int s = 0; s < NSEG; s++) {
        g_segoff[s * NE + e] = run;
        run += g_blkcnt[s * NE + e];
    }
    g_run[e] = run;
    g_cnt[e] = min(run, CAPACITY);
}

__global__ void __launch_bounds__(256) place_kernel() {
    __shared__ int s_wtot[8][NE];
    __shared__ int s_base[NE];
    int tid = threadIdx.x, wid = tid >> 5, lane = tid & 31;
    int i = blockIdx.x * 256 + tid;
    int e = g_te[i];
    int rank = 0;
#pragma unroll
    for (int ee = 0; ee < NE; ee++) {
        unsigned m = __ballot_sync(0xffffffffu, e == ee);
        if (e == ee) rank = __popc(m & ((1u << lane) - 1u));
        if (lane == 0) s_wtot[wid][ee] = __popc(m);
    }
    if (tid < NE) s_base[tid] = g_segoff[blockIdx.x * NE + tid];
    __syncthreads();
    int off = s_base[e];
    for (int w = 0; w < wid; w++) off += s_wtot[w][e];
    int pos = off + rank;
    if (pos < CAPACITY) {
        g_src[e * CAPACITY + pos] = i >> 1;
        g_cidx[i] = e * CAPACITY + pos;
        g_cw[i]   = g_tw[i];
    } else {
        g_cidx[i] = 0;
        g_cw[i]   = 0.f;
    }
}

__global__ void __launch_bounds__(256) pad_kernel() {
    int idx = blockIdx.x * 256 + threadIdx.x;
    if (idx >= NE * CAPACITY) return;
    int e = idx / CAPACITY, c = idx % CAPACITY;
    if (c >= g_cnt[e]) g_src[idx] = 0;
}

// ---------------- dispatch: gather x rows into chunked swizzled A ------------
__global__ void __launch_bounds__(256) dispatch_kernel(const float* __restrict__ x) {
    int slot = blockIdx.x;
    int e  = slot / CAPACITY;
    int sl = slot % CAPACITY;
    int mt = sl >> 8, row = sl & 255;
    int tok = g_src[slot];
    int t = threadIdx.x;
    int k = t >> 3, seg = t & 7;

    float4 v = *reinterpret_cast<const float4*>(x + (size_t)tok * DM + k * 32 + seg * 4);
    v.x = to_tf32(v.x); v.y = to_tf32(v.y); v.z = to_tf32(v.z); v.w = to_tf32(v.w);

    size_t cb = (((size_t)e * MT1 + mt) * NCH1 + k) * CHUNK_BYTES;
    uint32_t off = swz((uint32_t)(row * 128 + seg * 16));
    *reinterpret_cast<float4*>(reinterpret_cast<char*>(g_abuf) + cb + off) = v;
}

// ---------------- repack W: transpose + round + chunk + swizzle ---------------
__global__ void __launch_bounds__(256) repack_w_kernel(const float* __restrict__ W,
                                                       float* __restrict__ Wc,
                                                       int KD, int ND) {
    __shared__ float t[32][33];
    int e = blockIdx.z;
    int n0 = blockIdx.x * 32, k0 = blockIdx.y * 32;
    const float* src = W + (size_t)e * KD * ND;
    int tx = threadIdx.x & 31, ty = threadIdx.x >> 5;
#pragma unroll
    for (int r = 0; r < 32; r += 8)
        t[ty + r][tx] = src[(size_t)(k0 + ty + r) * ND + n0 + tx];
    __syncthreads();
    int nchunks = KD >> 5;
    int chunk = k0 >> 5;
#pragma unroll
    for (int r = 0; r < 32; r += 8) {
        int n = n0 + ty + r;
        int k = k0 + tx;
        float val = to_tf32(t[tx][ty + r]);
        size_t cb = (((size_t)e * (ND >> 8) + (n >> 8)) * nchunks + chunk) * CHUNK_BYTES;
        uint32_t off = swz((uint32_t)((n & 255) * 128 + (k & 31) * 4));
        *reinterpret_cast<float*>(reinterpret_cast<char*>(Wc) + cb + off) = val;
    }
}

// ---------------- grouped GEMM: cg2 pair tile 256x512, CTA-local barriers -----
#define STAGES 4
#define STAGE_BYTES (3*HALF_BYTES)         // per CTA: A half + B0 half + B1 half = 48KB
#define SMEM_SZ (2048 + STAGES*STAGE_BYTES)

// idesc cg2: c=F32(1<<4), a=TF32(2<<7), b=TF32(2<<10), N=256 (32<<17), M=256 (16<<24)
#define IDESC2 ((1u<<4) | (2u<<7) | (2u<<10) | (32u<<17) | (16u<<24))

template <int WHICH>
__global__ void __launch_bounds__(256, 1) __cluster_dims__(2, 1, 1)
moe_gemm_tc(const float* __restrict__ Wsrc, const float* __restrict__ Xsrc) {
    constexpr int Kd   = (WHICH == 1) ? DM : DFF;
    constexpr int Nd   = (WHICH == 1) ? DFF : DM;
    constexpr int NCH  = Kd / 32;
    constexpr int NTC  = (WHICH == 1) ? NT1 : NT2;

    int e  = blockIdx.z;
    int mt = blockIdx.x >> 1;
    int nt = blockIdx.y;                   // 512-wide n-tile
    int m0 = mt * 256;
    int n0 = nt * 512;
    if (m0 >= g_cnt[e]) return;

    extern __shared__ char smem[];
    int tid = threadIdx.x, wid = tid >> 5, lane = tid & 31;

#if HAS_TC
    (void)Wsrc; (void)Xsrc;
    uint32_t rank = cluster_rank();
    uint32_t sb = smem_u32(smem);
    uint32_t tmp_addr = sb;                       // tcgen05.alloc result
    uint32_t mb_full  = sb + 16;                  // 4 x 8B (own CTA)
    uint32_t mb_empty = sb + 48;                  // 4 x 8B (own CTA, multicast commit)
    uint32_t mb_ready = sb + 80;                  // 4 x 8B (used on rank 0 only)
    uint32_t mb_done  = sb + 112;
    uint32_t stage0 = (sb + 128 + 1023) & ~1023u;

    const char* abase;
    if (WHICH == 1) abase = reinterpret_cast<const char*>(g_abuf)
                          + (((size_t)e * MT1 + mt) * NCH1) * CHUNK_BYTES;
    else            abase = reinterpret_cast<const char*>(g_h)
                          + (((size_t)e * MT1 + mt) * NCH2) * CHUNK_BYTES;
    const float* wc = (WHICH == 1) ? g_w1t : g_w2t;
    const char* bbase0 = reinterpret_cast<const char*>(wc)
                       + (((size_t)e * NTC + (nt * 2 + 0)) * NCH) * CHUNK_BYTES;
    const char* bbase1 = reinterpret_cast<const char*>(wc)
                       + (((size_t)e * NTC + (nt * 2 + 1)) * NCH) * CHUNK_BYTES;
    size_t rk_off = (size_t)rank * HALF_BYTES;

    if (tid == 0) {
        for (int j = 0; j < STAGES; j++) {
            mbar_init(mb_full  + j * 8, 1);
            mbar_init(mb_empty + j * 8, 1);
            mbar_init(mb_ready + j * 8, 1);
        }
        mbar_init(mb_done, 1);
        FENCE_ASYNC_SHARED();
    }
    if (wid == 0) TC_ALLOC_CG2(tmp_addr, 512);
    __syncthreads();
    uint32_t tmem;
    asm volatile("ld.shared.b32 %0, [%1];" : "=r"(tmem) : "r"(tmp_addr));
    CLUSTER_SYNC();                                // peer barrier inits visible

    if (tid == 0) {
        // ---- producer (both CTAs): all completions CTA-LOCAL ----
        for (int i = 0; i < NCH; i++) {
            int s = i & 3, ep = i >> 2;
            if (i >= STAGES) mbar_wait(mb_empty + s * 8, (ep - 1) & 1);
            uint32_t st = stage0 + s * STAGE_BYTES;
            mbar_expect_tx(mb_full + s * 8, 3 * HALF_BYTES);
            bulk_g2s(st,                  abase  + (size_t)i * CHUNK_BYTES + rk_off, HALF_BYTES, mb_full + s * 8);
            bulk_g2s(st + HALF_BYTES,     bbase0 + (size_t)i * CHUNK_BYTES + rk_off, HALF_BYTES, mb_full + s * 8);
            bulk_g2s(st + 2 * HALF_BYTES, bbase1 + (size_t)i * CHUNK_BYTES + rk_off, HALF_BYTES, mb_full + s * 8);
        }
    } else if (tid == 32) {
        if (rank == 1) {
            // ---- relay: own data ready -> arrive leader's ready[s] ----
            for (int i = 0; i < NCH; i++) {
                int s = i & 3, ep = i >> 2;
                mbar_wait(mb_full + s * 8, ep & 1);
                mbar_arrive_rank0(mb_ready + s * 8);
            }
        } else {
            // ---- leader MMA: wait own full + peer ready ----
            for (int i = 0; i < NCH; i++) {
                int s = i & 3, ep = i >> 2;
                mbar_wait(mb_full + s * 8, ep & 1);
                mbar_wait_cluster(mb_ready + s * 8, ep & 1);
                uint64_t ad = mkdesc(stage0 + s * STAGE_BYTES);
                uint64_t b0 = mkdesc(stage0 + s * STAGE_BYTES + HALF_BYTES);
                uint64_t b1 = mkdesc(stage0 + s * STAGE_BYTES + 2 * HALF_BYTES);
#pragma unroll
                for (int st = 0; st < 4; st++) {
                    uint32_t en = (i > 0) || (st > 0);
                    mma_tf32_ss_cg2(tmem,       ad + st * 2, b0 + st * 2, IDESC2, en);
                    mma_tf32_ss_cg2(tmem + 256, ad + st * 2, b1 + st * 2, IDESC2, en);
                }
                TC_COMMIT_MC2(mb_empty + s * 8, 0x3);
            }
            TC_COMMIT_MC2(mb_done, 0x3);
        }
    }

    // ---- all threads (both CTAs): wait for final MMA, then epilogue ----
    mbar_wait(mb_done, 0);
    TC_FENCE_AFTER();

    int part = wid & 3, half = wid >> 2;
    int lrow = part * 32 + lane;                         // row within this CTA's 128
    uint32_t dbase = tmem + half * 256;
    if (WHICH == 1) {
        char* hb = reinterpret_cast<char*>(g_h)
                 + (((size_t)e * MT1 + mt) * NCH2 + (size_t)(nt * 16 + half * 8)) * CHUNK_BYTES;
        int crow = (int)rank * 128 + lrow;               // row within 256-row chunk
#pragma unroll
        for (int b = 0; b < 8; b++) {
            uint32_t u[32];
            TC_LD_X32(u, dbase + b * 32);
            TC_WAIT_LD();
            char* cb = hb + (size_t)b * CHUNK_BYTES;
#pragma unroll
            for (int c = 0; c < 32; c += 4) {
                float4 v = make_float4(
                    to_tf32(gelu_tanh(__uint_as_float(u[c + 0]))),
                    to_tf32(gelu_tanh(__uint_as_float(u[c + 1]))),
                    to_tf32(gelu_tanh(__uint_as_float(u[c + 2]))),
                    to_tf32(gelu_tanh(__uint_as_float(u[c + 3]))));
                uint32_t off = swz((uint32_t)(crow * 128 + (c >> 2) * 16));
                *reinterpret_cast<float4*>(cb + off) = v;
            }
        }
    } else {
        int grow = m0 + (int)rank * 128 + lrow;
        float* outp = g_y + ((size_t)(e * CAPACITY + grow)) * Nd + n0 + half * 256;
#pragma unroll
        for (int b = 0; b < 8; b++) {
            uint32_t u[32];
            TC_LD_X32(u, dbase + b * 32);
            TC_WAIT_LD();
#pragma unroll
            for (int c = 0; c < 32; c += 4) {
                float4 v = make_float4(__uint_as_float(u[c + 0]), __uint_as_float(u[c + 1]),
                                       __uint_as_float(u[c + 2]), __uint_as_float(u[c + 3]));
                *reinterpret_cast<float4*>(outp + b * 32 + c) = v;
            }
        }
    }
    TC_FENCE_BEFORE();
    __syncthreads();
    CLUSTER_SYNC();
    if (wid == 0) {
        TC_RELINQ_CG2();
        TC_DEALLOC_CG2(tmem, 512);
    }
    CLUSTER_SYNC();
#else
    // ================= tf32 wmma fallback (each CTA: 128 rows x 512 cols) =====
    using namespace nvcuda;
    constexpr int BM = 128;
    constexpr int BNF = 256;
    constexpr int BK = 16;
    constexpr int NKS = Kd / BK;
    int rank = blockIdx.x & 1;
    int m0h = m0 + rank * 128;
    const float* We = Wsrc + (size_t)e * Kd * Nd;
    float* As = reinterpret_cast<float*>(smem);
    float* Bs = As + 2 * BM * (BK + 4);
    const float** s_arow = reinterpret_cast<const float**>(Bs + 2 * BK * (BNF + 8));

    for (int r = tid; r < BM; r += 256) {
        if (WHICH == 1) s_arow[r] = Xsrc + (size_t)g_src[e * CAPACITY + m0h + r] * Kd;
        else            s_arow[r] = g_h + (size_t)(e * CAPACITY + m0h + r) * Kd;
    }
    __syncthreads();
    auto Aat = [&](int buf, int r, int c) -> float& { return As[(buf * BM + r) * (BK + 4) + c]; };
    auto Bat = [&](int buf, int r, int c) -> float& { return Bs[(buf * BK + r) * (BNF + 8) + c]; };

    for (int hp = 0; hp < 2; hp++) {
        int n0h = n0 + hp * BNF;
        auto loadA = [&](int buf, int k0) {
#pragma unroll
            for (int it = 0; it < 2; it++) {
                int idx = tid * 2 + it;
                int r = idx >> 2, q = idx & 3;
                float4 v = *reinterpret_cast<const float4*>(s_arow[r] + k0 + q * 4);
                *reinterpret_cast<float4*>(&Aat(buf, r, q * 4)) = v;
            }
        };
        auto loadB = [&](int buf, int k0) {
#pragma unroll
            for (int it = 0; it < 4; it++) {
                int idx = tid + it * 256;
                int r = idx >> 6, c = idx & 63;
                float4 v = *reinterpret_cast<const float4*>(We + (size_t)(k0 + r) * Nd + n0h + c * 4);
                *reinterpret_cast<float4*>(&Bat(buf, r, c * 4)) = v;
            }
        };
        typedef wmma::fragment<wmma::matrix_a, 16, 16, 8, wmma::precision::tf32, wmma::row_major> FragA;
        typedef wmma::fragment<wmma::matrix_b, 16, 16, 8, wmma::precision::tf32, wmma::row_major> FragB;
        typedef wmma::fragment<wmma::accumulator, 16, 16, 8, float> FragC;
        FragC acc[4][4];
#pragma unroll
        for (int i = 0; i < 4; i++)
#pragma unroll
            for (int j = 0; j < 4; j++) wmma::fill_fragment(acc[i][j], 0.f);
        int wm = wid >> 2, wn = wid & 3;
        loadA(0, 0); loadB(0, 0);
        __syncthreads();
        for (int ks = 0; ks < NKS; ks++) {
            int cur = ks & 1;
            if (ks + 1 < NKS) { loadA(cur ^ 1, (ks + 1) * BK); loadB(cur ^ 1, (ks + 1) * BK); }
#pragma unroll
            for (int kk = 0; kk < 2; kk++) {
                FragA af[2]; FragB bf[4];
#pragma unroll
                for (int i = 0; i < 2; i++) {
                    wmma::load_matrix_sync(af[i], &Aat(cur, wm * 64 + i * 32 + 0, kk * 8), BK + 4);
#pragma unroll
                    for (int t = 0; t < af[i].num_elements; t++)
                        af[i].x[t] = wmma::__float_to_tf32(af[i].x[t]);
                }
#pragma unroll
                for (int j = 0; j < 4; j++) {
                    wmma::load_matrix_sync(bf[j], &Bat(cur, kk * 8, wn * 64 + j * 16), BNF + 8);
#pragma unroll
                    for (int t = 0; t < bf[j].num_elements; t++)
                        bf[j].x[t] = wmma::__float_to_tf32(bf[j].x[t]);
                }
#pragma unroll
                for (int i = 0; i < 2; i++)
#pragma unroll
                    for (int j = 0; j < 4; j++)
                        wmma::mma_sync(acc[i][j], af[i], bf[j], acc[i][j]);
                FragA ag[2];
#pragma unroll
                for (int i = 0; i < 2; i++) {
                    wmma::load_matrix_sync(ag[i], &Aat(cur, wm * 64 + i * 32 + 16, kk * 8), BK + 4);
#pragma unroll
                    for (int t = 0; t < ag[i].num_elements; t++)
                        ag[i].x[t] = wmma::__float_to_tf32(ag[i].x[t]);
                }
#pragma unroll
                for (int i = 0; i < 2; i++)
#pragma unroll
                    for (int j = 0; j < 4; j++)
                        wmma::mma_sync(acc[i + 2][j], ag[i], bf[j], acc[i + 2][j]);
            }
            __syncthreads();
        }
        float* Cb = ((WHICH == 1) ? g_h : g_y) + (size_t)(e * CAPACITY + m0h) * Nd + n0h;
#pragma unroll
        for (int i = 0; i < 4; i++)
#pragma unroll
            for (int j = 0; j < 4; j++) {
                int rowoff = wm * 64 + (i & 1) * 32 + (i >> 1) * 16;
                if (WHICH == 1) {
#pragma unroll
                    for (int t = 0; t < acc[i][j].num_elements; t++)
                        acc[i][j].x[t] = to_tf32(gelu_tanh(acc[i][j].x[t]));
                }
                wmma::store_matrix_sync(Cb + (size_t)rowoff * Nd + wn * 64 + j * 16,
                                        acc[i][j], Nd, wmma::mem_row_major);
            }
        __syncthreads();
    }
#endif
}

// ---------------- combine -----------------------------------------------------
__global__ void __launch_bounds__(256) combine_kernel(float* __restrict__ out) {
    int t   = blockIdx.x;
    int tid = threadIdx.x;
    int i0 = g_cidx[2 * t],     i1 = g_cidx[2 * t + 1];
    float w0 = g_cw[2 * t],     w1 = g_cw[2 * t + 1];
    const float4* y0 = reinterpret_cast<const float4*>(g_y + (size_t)i0 * DM);
    const float4* y1 = reinterpret_cast<const float4*>(g_y + (size_t)i1 * DM);
    float4 a = y0[tid], b = y1[tid];
    float4 r;
    r.x = w0 * a.x + w1 * b.x;
    r.y = w0 * a.y + w1 * b.y;
    r.z = w0 * a.z + w1 * b.z;
    r.w = w0 * a.w + w1 * b.w;
    reinterpret_cast<float4*>(out + (size_t)t * DM)[tid] = r;
}

// ---------------- launch ------------------------------------------------------
extern "C" void kernel_launch(void* const* d_in, const int* in_sizes, int n_in,
                              void* d_out, int out_size) {
    const float* x  = (const float*)d_in[0];   // [T, D]
    const float* Wg = (const float*)d_in[1];   // [D, E]
    const float* W1 = (const float*)d_in[2];   // [E, D, H]
    const float* W2 = (const float*)d_in[3];   // [E, H, D]
    float* out = (float*)d_out;                // [T, D]

    cudaFuncSetAttribute(moe_gemm_tc<1>, cudaFuncAttributeMaxDynamicSharedMemorySize, SMEM_SZ);
    cudaFuncSetAttribute(moe_gemm_tc<2>, cudaFuncAttributeMaxDynamicSharedMemorySize, SMEM_SZ);

    router_kernel<<<NT / 8, 256>>>(x, Wg);
    {
        float* w1t; cudaGetSymbolAddress((void**)&w1t, g_w1t);
        repack_w_kernel<<<dim3(DFF / 32, DM / 32, NE), 256>>>(W1, w1t, DM, DFF);
    }
    {
        float* w2t; cudaGetSymbolAddress((void**)&w2t, g_w2t);
        repack_w_kernel<<<dim3(DM / 32, DFF / 32, NE), 256>>>(W2, w2t, DFF, DM);
    }
    hist_kernel<<<NSEG, 256>>>();
    prefix_kernel<<<1, 32>>>();
    place_kernel<<<NSEG, 256>>>();
    pad_kernel<<<(NE * CAPACITY + 255) / 256, 256>>>();
    dispatch_kernel<<<NE * CAPACITY, 256>>>(x);
    moe_gemm_tc<1><<<dim3(MT1 * 2, DFF / 512, NE), 256, SMEM_SZ>>>(W1, x);
    moe_gemm_tc<2><<<dim3(MT1 * 2, DM  / 512, NE), 256, SMEM_SZ>>>(W2, x);
    combine_kernel<<<NT, 256>>>(out);
}